// round 8
// baseline (speedup 1.0000x reference)
#include <cuda_runtime.h>
#include <math.h>

// Problem constants: S=16 samples, B=128 batch, T=200 steps, L=64 latent,
// R=16 rank, H=256 hidden. One persistent CTA per batch element.
#define S_DIM 16
#define B_DIM 128
#define T_DIM 200
#define L_DIM 64
#define R_DIM 16
#define H_DIM 256
#define NT    256   // threads per CTA
#define LP    65    // padded row stride for 64x64 matrices (conflict-free columns)
#define HS    260   // padded row stride for hidden activations (float4-able)
#define KP    17    // padded row stride for K tile

struct __align__(16) SmemNLF {
  float w1[L_DIM * H_DIM];   // (L,H) row-major
  float w2[H_DIM * L_DIM];   // (H,L) row-major
  float b1[H_DIM];
  float b2[L_DIM];
  float zs[S_DIM * L_DIM];   // z_prev  [s][l]
  float hid[S_DIM * HS];     // tanh(layer1) [s][h]
  float ms[S_DIM * L_DIM];   // mean_fn output [s][l]
  float A [L_DIM * LP];      // workspace: P_p then J_f (full symmetric)
  float Lb[L_DIM * LP];      // cholesky factor (zeros above diag)
  float Li[L_DIM * LP];      // triangular inverse (zeros above diag)
  float Ksm[L_DIM * KP];     // K_t as (L,R)
  float wsm[S_DIM * L_DIM];  // w_t [s][l]
  float kt[L_DIM];
  float mp[L_DIM];
  float hf[L_DIM];
  float mf[L_DIM];
  float yv[L_DIM];
  float invd[L_DIM];
  float Qs[L_DIM];
  float m0s[L_DIM];
  float J0s[L_DIM];
  float sqP0[L_DIM];
};

__device__ __forceinline__ float softplus_f(float x) {
  // jax.nn.softplus = logaddexp(x, 0) = max(x,0) + log1p(exp(-|x|))
  return fmaxf(x, 0.0f) + log1pf(expf(-fabsf(x)));
}

// Right-looking Cholesky of A (64x64, lower triangle valid) into Lb
// (full matrix, exact zeros above the diagonal). One __syncthreads per
// column. A's trailing lower triangle is destroyed; column j of A stays
// raw during iteration j so the scale and the update never conflict.
__device__ __forceinline__ void chol64(float* __restrict__ A,
                                       float* __restrict__ Lb, int tid) {
  const int i = tid & 63;
  const int g = tid >> 6;          // 0..3 residue class for trailing update
  const int iwmax = i | 31;        // warp-uniform max row in this warp
  for (int j = 0; j < 64; ++j) {
    float d = A[j * LP + j];       // broadcast
    float sinv = rsqrtf(d);        // 1/sqrt(d)
    if (g == 0)
      Lb[i * LP + j] = (i >= j) ? A[i * LP + j] * sinv : 0.0f;
    if (j < iwmax) {
      float f = A[i * LP + j] * (sinv * sinv);   // A[i][j]/d
      int kk = j + 1;
      kk += (g - kk) & 3;          // align kk to this thread's residue class
      for (; kk < 64; kk += 4)
        if (kk <= i) A[i * LP + kk] -= f * A[kk * LP + j];
    }
    __syncthreads();
  }
}

// Li = Lb^{-1} (lower). Deferred-scaling column-parallel forward
// substitution: 4 threads per column (16 rows each), one barrier per step,
// single final scaling pass. Fills exact zeros above the diagonal so all
// downstream consumers can run full / warp-uniform-truncated loops.
__device__ __forceinline__ void triinv64(const float* __restrict__ Lb,
                                         float* __restrict__ Li,
                                         const float* __restrict__ invd,
                                         int tid) {
  for (int idx = tid; idx < 64 * 64; idx += NT) {
    int r = idx >> 6, c = idx & 63;
    Li[r * LP + c] = (r == c) ? 1.0f : 0.0f;
  }
  const int c  = tid & 63;
  const int p  = tid >> 6;
  const int r0 = p * 16, r1 = r0 + 16;
  const int cw = c & 32;           // warp-uniform min column in this warp
  __syncthreads();
  for (int j = 0; j < 63; ++j) {
    if (j >= cw) {                 // x_j == 0 for all columns of this warp otherwise
      float xj = Li[j * LP + c] * invd[j];
      int st = (j + 1 > r0) ? (j + 1) : r0;
      for (int r = st; r < r1; ++r)
        Li[r * LP + c] -= Lb[r * LP + j] * xj;
    }
    __syncthreads();
  }
  for (int idx = tid; idx < 64 * 64; idx += NT) {
    int r = idx >> 6, c2 = idx & 63;
    Li[r * LP + c2] *= invd[r];
  }
  __syncthreads();
}

// Load per-step inputs k_t, K_t, w_t into SMEM (all coalesced / float4).
__device__ __forceinline__ void load_step(SmemNLF* sm,
    const float* __restrict__ gk, const float* __restrict__ gK,
    const float* __restrict__ gw, int b, int t, int tid) {
  if (tid < L_DIM)
    sm->kt[tid] = gk[((size_t)b * T_DIM + t) * L_DIM + tid];
  {
    // K_t: 1024 contiguous floats -> Ksm (L, KP)
    const float4* src =
        (const float4*)(gK + ((size_t)b * T_DIM + t) * (L_DIM * R_DIM));
    float4 v = src[tid];
    int l = tid >> 2, r = (tid & 3) * 4;
    float* dst = &sm->Ksm[l * KP + r];
    dst[0] = v.x; dst[1] = v.y; dst[2] = v.z; dst[3] = v.w;
  }
  {
    // w_t: 16 rows of 64 contiguous floats
    int s = tid >> 4, l4 = (tid & 15) * 4;
    const float4* src = (const float4*)(
        gw + (((size_t)t * S_DIM + s) * B_DIM + b) * L_DIM + l4);
    *(float4*)&sm->wsm[s * L_DIM + l4] = *src;
  }
}

// z_f[s][i] = mf[i] + sum_j Li[j][i] * w[s][j]  (Li = Lf^{-1}; L^{-T} matvec)
// Also writes zs (next-step MLP input) and the z_f output slab.
__device__ __forceinline__ void zf_store(SmemNLF* sm, float* __restrict__ out_z,
                                         int b, int t, int tid) {
  const int i = tid & 63, p = tid >> 6;
  const float base = sm->mf[i];
  float a0 = base, a1 = base, a2 = base, a3 = base;
  const float* wr0 = &sm->wsm[(4 * p + 0) * L_DIM];
  const float* wr1 = &sm->wsm[(4 * p + 1) * L_DIM];
  const float* wr2 = &sm->wsm[(4 * p + 2) * L_DIM];
  const float* wr3 = &sm->wsm[(4 * p + 3) * L_DIM];
  const int j0 = i & 32;           // warp-uniform; Li[j][i]==0 for j<i
  for (int j = j0; j < 64; ++j) {
    float lv = sm->Li[j * LP + i];
    a0 += lv * wr0[j]; a1 += lv * wr1[j];
    a2 += lv * wr2[j]; a3 += lv * wr3[j];
  }
  float acc[4] = {a0, a1, a2, a3};
#pragma unroll
  for (int q = 0; q < 4; ++q) {
    int s = 4 * p + q;
    sm->zs[s * L_DIM + i] = acc[q];
    out_z[(((size_t)s * B_DIM + b) * T_DIM + t) * L_DIM + i] = acc[q];
  }
}

extern __shared__ float smem_raw_nlf[];

__global__ void __launch_bounds__(NT, 1)
NonlinearFilter_24721831756601_kernel(
    const float* __restrict__ gk,     // (B,T,L)
    const float* __restrict__ gK,     // (B,T,L,R)
    const float* __restrict__ glogQ,  // (L)
    const float* __restrict__ gm0,    // (L)
    const float* __restrict__ glogv0, // (L)
    const float* __restrict__ gW1,    // (L,H)
    const float* __restrict__ gb1,    // (H)
    const float* __restrict__ gW2,    // (H,L)
    const float* __restrict__ gb2,    // (L)
    const float* __restrict__ gw,     // (T,S,B,L)
    float* __restrict__ out) {
  SmemNLF* sm = (SmemNLF*)smem_raw_nlf;
  const int tid = threadIdx.x;
  const int b = blockIdx.x;

  const size_t ZN = (size_t)S_DIM * B_DIM * T_DIM * L_DIM;
  const size_t MN = (size_t)B_DIM * T_DIM * L_DIM;
  const size_t PN = (size_t)B_DIM * T_DIM * L_DIM * L_DIM;
  float* out_z  = out;             // z_f     (S,B,T,L)
  float* out_mf = out + ZN;        // m_f     (B,T,L)
  float* out_mp = out_mf + MN;     // m_p     (B,T,L)
  float* out_Pf = out_mp + MN;     // P_f_chol(B,T,L,L)
  float* out_Pp = out_Pf + PN;     // P_p_chol(B,T,L,L)

  // ---- one-time loads ----
  for (int idx = tid; idx < L_DIM * H_DIM; idx += NT) sm->w1[idx] = gW1[idx];
  for (int idx = tid; idx < H_DIM * L_DIM; idx += NT) sm->w2[idx] = gW2[idx];
  if (tid < H_DIM) sm->b1[tid] = gb1[tid];
  if (tid < L_DIM) {
    sm->b2[tid]  = gb2[tid];
    sm->Qs[tid]  = softplus_f(glogQ[tid]);
    float p0     = softplus_f(glogv0[tid]);
    sm->J0s[tid] = 1.0f / p0;
    sm->sqP0[tid] = sqrtf(p0);
    sm->m0s[tid] = gm0[tid];
  }
  load_step(sm, gk, gK, gw, b, 0, tid);
  __syncthreads();

  // ================= t = 0 =================
  // Jf0 = diag(J0) + K0 K0^T   (full symmetric fill)
  for (int idx = tid; idx < 64 * 64; idx += NT) {
    int i = idx >> 6, j = idx & 63;
    float acc = (i == j) ? sm->J0s[i] : 0.0f;
#pragma unroll
    for (int r = 0; r < R_DIM; ++r)
      acc += sm->Ksm[i * KP + r] * sm->Ksm[j * KP + r];
    sm->A[i * LP + j] = acc;
  }
  if (tid < L_DIM)  // h_f0 = J0*m0 + k0  (same-thread values only)
    sm->hf[tid] = sm->J0s[tid] * sm->m0s[tid] + sm->kt[tid];
  __syncthreads();

  chol64(sm->A, sm->Lb, tid);
  if (tid < L_DIM) sm->invd[tid] = __fdividef(1.0f, sm->Lb[tid * LP + tid]);
  triinv64(sm->Lb, sm->Li, sm->invd, tid);   // Li = Lf0^{-1}

  // yv = Li * hf ; meanwhile write P_p_chol0 (diag sqrt(P0)) and m_p0
  if (tid < L_DIM) {
    float acc = 0.0f;
    int jend = (tid | 31) + 1;
    for (int j = 0; j < jend; ++j) acc += sm->Li[tid * LP + j] * sm->hf[j];
    sm->yv[tid] = acc;
    out_mp[((size_t)b * T_DIM + 0) * L_DIM + tid] = sm->m0s[tid];
  }
  {
    float* dst = out_Pp + ((size_t)b * T_DIM + 0) * (L_DIM * L_DIM);
    for (int idx = tid; idx < 64 * 64; idx += NT) {
      int i = idx >> 6, j = idx & 63;
      dst[idx] = (i == j) ? sm->sqP0[i] : 0.0f;
    }
  }
  __syncthreads();
  // mf = Li^T * yv ; write m_f0 and P_f_chol0 = Li^T
  if (tid < L_DIM) {
    float acc = 0.0f;
    for (int j = tid & 32; j < 64; ++j) acc += sm->Li[j * LP + tid] * sm->yv[j];
    sm->mf[tid] = acc;
    out_mf[((size_t)b * T_DIM + 0) * L_DIM + tid] = acc;
  }
  {
    float* dst = out_Pf + ((size_t)b * T_DIM + 0) * (L_DIM * L_DIM);
    for (int idx = tid; idx < 64 * 64; idx += NT) {
      int i = idx >> 6, j = idx & 63;
      dst[idx] = sm->Li[j * LP + i];
    }
  }
  __syncthreads();
  zf_store(sm, out_z, b, 0, tid);
  __syncthreads();

  // ================= t = 1 .. T-1 =================
  for (int t = 1; t < T_DIM; ++t) {
    load_step(sm, gk, gK, gw, b, t, tid);

    // ---- MLP layer 1: hid[s][h] = tanh(b1[h] + sum_l zs[s][l] W1[l][h]) ----
    {
      float acc[S_DIM];
      float bb = sm->b1[tid];
#pragma unroll
      for (int s = 0; s < S_DIM; ++s) acc[s] = bb;
      for (int l = 0; l < L_DIM; l += 4) {
        float wa = sm->w1[(l + 0) * H_DIM + tid];
        float wb = sm->w1[(l + 1) * H_DIM + tid];
        float wc = sm->w1[(l + 2) * H_DIM + tid];
        float wd = sm->w1[(l + 3) * H_DIM + tid];
#pragma unroll
        for (int s = 0; s < S_DIM; ++s) {
          float4 z4 = *(const float4*)&sm->zs[s * L_DIM + l];
          acc[s] += z4.x * wa + z4.y * wb + z4.z * wc + z4.w * wd;
        }
      }
#pragma unroll
      for (int s = 0; s < S_DIM; ++s) sm->hid[s * HS + tid] = tanhf(acc[s]);
    }
    __syncthreads();

    // ---- MLP layer 2: ms[s][j] = b2[j] + sum_h hid[s][h] W2[h][j] ----
    {
      const int j = tid & 63, p = tid >> 6;
      float acc[4];
      float bb = sm->b2[j];
#pragma unroll
      for (int q = 0; q < 4; ++q) acc[q] = bb;
      for (int h = 0; h < H_DIM; h += 4) {
        float wa = sm->w2[(h + 0) * L_DIM + j];
        float wb = sm->w2[(h + 1) * L_DIM + j];
        float wc = sm->w2[(h + 2) * L_DIM + j];
        float wd = sm->w2[(h + 3) * L_DIM + j];
#pragma unroll
        for (int q = 0; q < 4; ++q) {
          float4 h4 = *(const float4*)&sm->hid[(4 * p + q) * HS + h];
          acc[q] += h4.x * wa + h4.y * wb + h4.z * wc + h4.w * wd;
        }
      }
#pragma unroll
      for (int q = 0; q < 4; ++q) sm->ms[(4 * p + q) * L_DIM + j] = acc[q];
    }
    __syncthreads();

    // ---- m_p = mean_s ms ----
    if (tid < L_DIM) {
      float acc = 0.0f;
#pragma unroll
      for (int s = 0; s < S_DIM; ++s) acc += sm->ms[s * L_DIM + tid];
      sm->mp[tid] = acc * (1.0f / (float)S_DIM);
    }
    __syncthreads();

    // ---- P_p = diag(Q) + Ezz - mp mp^T ----
    for (int idx = tid; idx < 64 * 64; idx += NT) {
      int i = idx >> 6, j = idx & 63;
      float acc = 0.0f;
#pragma unroll
      for (int s = 0; s < S_DIM; ++s)
        acc += sm->ms[s * L_DIM + i] * sm->ms[s * L_DIM + j];
      acc = acc * (1.0f / (float)S_DIM) - sm->mp[i] * sm->mp[j];
      if (i == j) acc += sm->Qs[i];
      sm->A[i * LP + j] = acc;
    }
    __syncthreads();

    chol64(sm->A, sm->Lb, tid);                       // Lb = Lp
    if (tid < L_DIM) sm->invd[tid] = __fdividef(1.0f, sm->Lb[tid * LP + tid]);
    triinv64(sm->Lb, sm->Li, sm->invd, tid);          // Li = Lp^{-1}

    // yv = Li * mp ; write P_p_chol (=Lp) and m_p outputs
    if (tid < L_DIM) {
      float acc = 0.0f;
      int jend = (tid | 31) + 1;
      for (int j = 0; j < jend; ++j) acc += sm->Li[tid * LP + j] * sm->mp[j];
      sm->yv[tid] = acc;
      out_mp[((size_t)b * T_DIM + t) * L_DIM + tid] = sm->mp[tid];
    }
    {
      float* dst = out_Pp + ((size_t)b * T_DIM + t) * (L_DIM * L_DIM);
      for (int idx = tid; idx < 64 * 64; idx += NT) {
        int i = idx >> 6, j = idx & 63;
        dst[idx] = sm->Lb[i * LP + j];
      }
    }
    __syncthreads();

    // hf = Li^T yv + k_t ; meanwhile J_f = Li^T Li + K K^T into A
    if (tid < L_DIM) {
      float acc = sm->kt[tid];
      for (int j = tid & 32; j < 64; ++j) acc += sm->Li[j * LP + tid] * sm->yv[j];
      sm->hf[tid] = acc;
    }
    for (int idx = tid; idx < 64 * 64; idx += NT) {
      int i = idx >> 6, j = idx & 63;
      float acc = 0.0f;
      int k0 = (i > (j & 32)) ? i : (j & 32);  // warp-uniform; zeros skipped
      for (int k2 = k0; k2 < 64; ++k2)
        acc += sm->Li[k2 * LP + i] * sm->Li[k2 * LP + j];
#pragma unroll
      for (int r = 0; r < R_DIM; ++r)
        acc += sm->Ksm[i * KP + r] * sm->Ksm[j * KP + r];
      sm->A[i * LP + j] = acc;
    }
    __syncthreads();

    chol64(sm->A, sm->Lb, tid);                       // Lb = Lf
    if (tid < L_DIM) sm->invd[tid] = __fdividef(1.0f, sm->Lb[tid * LP + tid]);
    triinv64(sm->Lb, sm->Li, sm->invd, tid);          // Li = Lf^{-1}

    // yv = Li * hf ; write P_f_chol = Li^T
    if (tid < L_DIM) {
      float acc = 0.0f;
      int jend = (tid | 31) + 1;
      for (int j = 0; j < jend; ++j) acc += sm->Li[tid * LP + j] * sm->hf[j];
      sm->yv[tid] = acc;
    }
    {
      float* dst = out_Pf + ((size_t)b * T_DIM + t) * (L_DIM * L_DIM);
      for (int idx = tid; idx < 64 * 64; idx += NT) {
        int i = idx >> 6, j = idx & 63;
        dst[idx] = sm->Li[j * LP + i];
      }
    }
    __syncthreads();

    // mf = Li^T yv ; write m_f
    if (tid < L_DIM) {
      float acc = 0.0f;
      for (int j = tid & 32; j < 64; ++j) acc += sm->Li[j * LP + tid] * sm->yv[j];
      sm->mf[tid] = acc;
      out_mf[((size_t)b * T_DIM + t) * L_DIM + tid] = acc;
    }
    __syncthreads();

    zf_store(sm, out_z, b, t, tid);
    __syncthreads();
  }
}

extern "C" void kernel_launch(void* const* d_in, const int* in_sizes, int n_in,
                              void* d_out, int out_size) {
  (void)in_sizes; (void)n_in; (void)out_size;
  static int attr_set = 0;
  if (!attr_set) {
    cudaFuncSetAttribute(NonlinearFilter_24721831756601_kernel,
                         cudaFuncAttributeMaxDynamicSharedMemorySize,
                         (int)sizeof(SmemNLF));
    attr_set = 1;
  }
  NonlinearFilter_24721831756601_kernel
      <<<B_DIM, NT, sizeof(SmemNLF)>>>(
          (const float*)d_in[0],  // k      (B,T,L)
          (const float*)d_in[1],  // K      (B,T,L,R)
          (const float*)d_in[2],  // log_Q  (L)
          (const float*)d_in[3],  // m0     (L)
          (const float*)d_in[4],  // log_v0 (L)
          (const float*)d_in[5],  // W1     (L,H)
          (const float*)d_in[6],  // b1     (H)
          (const float*)d_in[7],  // W2     (H,L)
          (const float*)d_in[8],  // b2     (L)
          (const float*)d_in[9],  // w      (T,S,B,L)
          (float*)d_out);
}

// round 9
// speedup vs baseline: 3.1198x; 3.1198x over previous
#include <cuda_runtime.h>
#include <math.h>

#define S_DIM 16
#define B_DIM 128
#define T_DIM 200
#define L_DIM 64
#define R_DIM 16
#define H_DIM 256
#define NT    256
#define LP    65    // padded stride, 64x64 matrices
#define LT    68    // padded stride for LbT (float4 rows)
#define HS    260   // padded stride for hidden
#define KP    17    // padded stride for K tile

struct __align__(16) SmemNLF {
  float w1[L_DIM * H_DIM];
  float w2[H_DIM * L_DIM];
  float b1[H_DIM];
  float b2[L_DIM];
  float zs[S_DIM * L_DIM];
  float hid[S_DIM * HS];
  float ms[S_DIM * L_DIM];
  float Lb[L_DIM * LP];      // cholesky factor, row-major, zeros above diag
  float LbT[L_DIM * LT];     // transposed factor (row j = column j of L)
  float Li[L_DIM * LP];      // inverse factor, zeros above diag
  float Ksm[L_DIM * KP];
  float wsm[S_DIM * L_DIM];
  float colbuf[2][72];       // chol column broadcast (double buffered)
  float ybuf[2][72];         // triinv pivot broadcast (double buffered)
  float kt[L_DIM];
  float mp[L_DIM];
  float hf[L_DIM];
  float mf[L_DIM];
  float yv[L_DIM];
  float invd[L_DIM];
  float Qs[L_DIM];
  float m0s[L_DIM];
  float J0s[L_DIM];
  float sqP0[L_DIM];
};

__device__ __forceinline__ float softplus_f(float x) {
  return fmaxf(x, 0.0f) + log1pf(expf(-fabsf(x)));
}

// Register-resident right-looking Cholesky. Thread (i,g) owns A[i][16g+q]
// in a[16] (strict upper-triangle entries may hold garbage; never consumed).
// One barrier per column; updates run on registers with broadcast LDS only.
__device__ __forceinline__ void chol64_reg(float* a, SmemNLF* sm,
                                           const int i, const int g) {
#pragma unroll 1
  for (int jg = 0; jg < 4; ++jg) {
    const bool owner = (g == jg);
#pragma unroll
    for (int q = 0; q < 16; ++q) {
      const int j = jg * 16 + q;
      float* cb = sm->colbuf[q & 1];
      if (owner) cb[i] = a[q];
      __syncthreads();
      float d = cb[j];
      float sinv = rsqrtf(d);
      if (g == 0) {
        float lv = (i >= j) ? cb[i] * sinv : 0.0f;
        sm->Lb[i * LP + j] = lv;
        sm->LbT[j * LT + i] = lv;
        if (i == j) sm->invd[j] = sinv;
      }
      if (j < (g << 4) + 15) {          // warp-uniform: group has cols > j
        float f = cb[i] * (sinv * sinv);
        float cv[16];
        const float4* c4 = (const float4*)&cb[g << 4];
        *(float4*)&cv[0]  = c4[0];
        *(float4*)&cv[4]  = c4[1];
        *(float4*)&cv[8]  = c4[2];
        *(float4*)&cv[12] = c4[3];
#pragma unroll
        for (int qq = 0; qq < 16; ++qq)
          if ((g << 4) + qq > j) a[qq] -= f * cv[qq];
      }
    }
  }
}

// Register-resident Li = L^{-1} (lower, exact zeros above diagonal).
// Thread (c,p) owns rows [16p,16p+16) of column c as deferred residual x[16].
__device__ __forceinline__ void triinv64_reg(SmemNLF* sm,
                                             const int c, const int p) {
  const int cw = c & 32;                // warp-uniform
  float x[16];
#pragma unroll
  for (int q = 0; q < 16; ++q) x[q] = ((p * 16 + q) == c) ? 1.0f : 0.0f;
#pragma unroll 1
  for (int jg = 0; jg < 4; ++jg) {
    const bool owner = (p == jg);
#pragma unroll
    for (int q = 0; q < 16; ++q) {
      const int j = jg * 16 + q;
      float* yb = sm->ybuf[q & 1];
      if (owner) {
        float y = x[q] * sm->invd[j];
        yb[c] = y;
        sm->Li[j * LP + c] = y;         // final Li[j][c] (0 above diag)
      }
      __syncthreads();
      if (j >= cw && j < (p << 4) + 15) {
        float yj = yb[c];
        float lv[16];
        const float4* l4 = (const float4*)&sm->LbT[j * LT + (p << 4)];
        *(float4*)&lv[0]  = l4[0];
        *(float4*)&lv[4]  = l4[1];
        *(float4*)&lv[8]  = l4[2];
        *(float4*)&lv[12] = l4[3];
#pragma unroll
        for (int qq = 0; qq < 16; ++qq)
          if ((p << 4) + qq > j) x[qq] -= lv[qq] * yj;
      }
    }
  }
}

__device__ __forceinline__ void load_step(SmemNLF* sm,
    const float* __restrict__ gk, const float* __restrict__ gK,
    const float* __restrict__ gw, int b, int t, int tid) {
  if (tid < L_DIM)
    sm->kt[tid] = gk[((size_t)b * T_DIM + t) * L_DIM + tid];
  {
    const float4* src =
        (const float4*)(gK + ((size_t)b * T_DIM + t) * (L_DIM * R_DIM));
    float4 v = src[tid];
    int l = tid >> 2, r = (tid & 3) * 4;
    float* dst = &sm->Ksm[l * KP + r];
    dst[0] = v.x; dst[1] = v.y; dst[2] = v.z; dst[3] = v.w;
  }
  {
    int s = tid >> 4, l4 = (tid & 15) * 4;
    const float4* src = (const float4*)(
        gw + (((size_t)t * S_DIM + s) * B_DIM + b) * L_DIM + l4);
    *(float4*)&sm->wsm[s * L_DIM + l4] = *src;
  }
}

// z_f[s][i] = mf[i] + sum_j Li[j][i]*w[s][j]; writes zs and z_f output.
__device__ __forceinline__ void zf_store(SmemNLF* sm, float* __restrict__ out_z,
                                         int b, int t, int tid) {
  const int i = tid & 63, p = tid >> 6;
  const float base = sm->mf[i];
  float a0 = base, a1 = base, a2 = base, a3 = base;
  const float* wr0 = &sm->wsm[(4 * p + 0) * L_DIM];
  const float* wr1 = &sm->wsm[(4 * p + 1) * L_DIM];
  const float* wr2 = &sm->wsm[(4 * p + 2) * L_DIM];
  const float* wr3 = &sm->wsm[(4 * p + 3) * L_DIM];
  const int j0 = i & 32;
  for (int j = j0; j < 64; ++j) {
    float lv = sm->Li[j * LP + i];
    a0 += lv * wr0[j]; a1 += lv * wr1[j];
    a2 += lv * wr2[j]; a3 += lv * wr3[j];
  }
  float acc[4] = {a0, a1, a2, a3};
#pragma unroll
  for (int q = 0; q < 4; ++q) {
    int s = 4 * p + q;
    sm->zs[s * L_DIM + i] = acc[q];
    out_z[(((size_t)s * B_DIM + b) * T_DIM + t) * L_DIM + i] = acc[q];
  }
}

extern __shared__ float smem_raw_nlf[];

__global__ void __launch_bounds__(NT, 1)
NonlinearFilter_24721831756601_kernel(
    const float* __restrict__ gk, const float* __restrict__ gK,
    const float* __restrict__ glogQ, const float* __restrict__ gm0,
    const float* __restrict__ glogv0, const float* __restrict__ gW1,
    const float* __restrict__ gb1, const float* __restrict__ gW2,
    const float* __restrict__ gb2, const float* __restrict__ gw,
    float* __restrict__ out) {
  SmemNLF* sm = (SmemNLF*)smem_raw_nlf;
  const int tid = threadIdx.x;
  const int b = blockIdx.x;
  const int i = tid & 63;             // owned matrix row (chol) / column (triinv)
  const int g = tid >> 6;             // column group (chol) / row group (triinv)
  const int iw = i & 32;              // warp-uniform floor of i

  const size_t ZN = (size_t)S_DIM * B_DIM * T_DIM * L_DIM;
  const size_t MN = (size_t)B_DIM * T_DIM * L_DIM;
  const size_t PN = (size_t)B_DIM * T_DIM * L_DIM * L_DIM;
  float* out_z  = out;
  float* out_mf = out + ZN;
  float* out_mp = out_mf + MN;
  float* out_Pf = out_mp + MN;
  float* out_Pp = out_Pf + PN;

  for (int idx = tid; idx < L_DIM * H_DIM; idx += NT) sm->w1[idx] = gW1[idx];
  for (int idx = tid; idx < H_DIM * L_DIM; idx += NT) sm->w2[idx] = gW2[idx];
  if (tid < H_DIM) sm->b1[tid] = gb1[tid];
  if (tid < L_DIM) {
    sm->b2[tid]  = gb2[tid];
    sm->Qs[tid]  = softplus_f(glogQ[tid]);
    float p0     = softplus_f(glogv0[tid]);
    sm->J0s[tid] = 1.0f / p0;
    sm->sqP0[tid] = sqrtf(p0);
    sm->m0s[tid] = gm0[tid];
  }
  load_step(sm, gk, gK, gw, b, 0, tid);
  __syncthreads();

  float a[16];                         // register tile A[i][16g+q]

  // ================= t = 0 =================
  {
    // Jf0 = diag(J0) + K0 K0^T into registers
    float Ki[R_DIM];
#pragma unroll
    for (int r = 0; r < R_DIM; ++r) Ki[r] = sm->Ksm[i * KP + r];
#pragma unroll
    for (int q = 0; q < 16; ++q) {
      int jj = (g << 4) + q;
      float acc = (i == jj) ? sm->J0s[i] : 0.0f;
#pragma unroll
      for (int r = 0; r < R_DIM; ++r) acc += Ki[r] * sm->Ksm[jj * KP + r];
      a[q] = acc;
    }
    if (tid < L_DIM)
      sm->hf[tid] = sm->J0s[tid] * sm->m0s[tid] + sm->kt[tid];

    chol64_reg(a, sm, i, g);           // Lf0
    triinv64_reg(sm, i, g);            // Li = Lf0^{-1}

    if (tid < L_DIM) {
      float acc = 0.0f;
      int jend = (tid | 31) + 1;
      for (int j = 0; j < jend; ++j) acc += sm->Li[tid * LP + j] * sm->hf[j];
      sm->yv[tid] = acc;
      out_mp[((size_t)b * T_DIM + 0) * L_DIM + tid] = sm->m0s[tid];
    }
    {
      float* dst = out_Pp + ((size_t)b * T_DIM + 0) * (L_DIM * L_DIM);
      for (int idx = tid; idx < 64 * 64; idx += NT) {
        int r = idx >> 6, c2 = idx & 63;
        dst[idx] = (r == c2) ? sm->sqP0[r] : 0.0f;
      }
    }
    __syncthreads();
    if (tid < L_DIM) {
      float acc = 0.0f;
      for (int j = iw; j < 64; ++j) acc += sm->Li[j * LP + tid] * sm->yv[j];
      sm->mf[tid] = acc;
      out_mf[((size_t)b * T_DIM + 0) * L_DIM + tid] = acc;
    }
    {
      float* dst = out_Pf + ((size_t)b * T_DIM + 0) * (L_DIM * L_DIM);
      for (int idx = tid; idx < 64 * 64; idx += NT) {
        int r = idx >> 6, c2 = idx & 63;
        dst[idx] = sm->Li[c2 * LP + r];
      }
    }
    __syncthreads();
    zf_store(sm, out_z, b, 0, tid);
    __syncthreads();
  }

  // ================= t = 1 .. T-1 =================
  for (int t = 1; t < T_DIM; ++t) {
    load_step(sm, gk, gK, gw, b, t, tid);

    // ---- MLP layer 1 ----
    {
      float acc[S_DIM];
      float bb = sm->b1[tid];
#pragma unroll
      for (int s = 0; s < S_DIM; ++s) acc[s] = bb;
      for (int l = 0; l < L_DIM; l += 4) {
        float wa = sm->w1[(l + 0) * H_DIM + tid];
        float wb = sm->w1[(l + 1) * H_DIM + tid];
        float wc = sm->w1[(l + 2) * H_DIM + tid];
        float wd = sm->w1[(l + 3) * H_DIM + tid];
#pragma unroll
        for (int s = 0; s < S_DIM; ++s) {
          float4 z4 = *(const float4*)&sm->zs[s * L_DIM + l];
          acc[s] += z4.x * wa + z4.y * wb + z4.z * wc + z4.w * wd;
        }
      }
#pragma unroll
      for (int s = 0; s < S_DIM; ++s) sm->hid[s * HS + tid] = tanhf(acc[s]);
    }
    __syncthreads();

    // ---- MLP layer 2 ----
    {
      const int j = tid & 63, p = tid >> 6;
      float acc4[4];
      float bb = sm->b2[j];
#pragma unroll
      for (int q = 0; q < 4; ++q) acc4[q] = bb;
      for (int h = 0; h < H_DIM; h += 4) {
        float wa = sm->w2[(h + 0) * L_DIM + j];
        float wb = sm->w2[(h + 1) * L_DIM + j];
        float wc = sm->w2[(h + 2) * L_DIM + j];
        float wd = sm->w2[(h + 3) * L_DIM + j];
#pragma unroll
        for (int q = 0; q < 4; ++q) {
          float4 h4 = *(const float4*)&sm->hid[(4 * p + q) * HS + h];
          acc4[q] += h4.x * wa + h4.y * wb + h4.z * wc + h4.w * wd;
        }
      }
#pragma unroll
      for (int q = 0; q < 4; ++q) sm->ms[(4 * p + q) * L_DIM + j] = acc4[q];
    }
    __syncthreads();

    // ---- m_p ----
    if (tid < L_DIM) {
      float acc = 0.0f;
#pragma unroll
      for (int s = 0; s < S_DIM; ++s) acc += sm->ms[s * L_DIM + tid];
      sm->mp[tid] = acc * (1.0f / (float)S_DIM);
    }
    __syncthreads();

    // ---- P_p into registers: a[q] = Q_diag + Ezz - mp mp^T ----
    {
      const float* msb = &sm->ms[(g << 4)];
#pragma unroll
      for (int q = 0; q < 16; ++q) a[q] = 0.0f;
#pragma unroll
      for (int s = 0; s < S_DIM; ++s) {
        float msi = sm->ms[s * L_DIM + i];
        const float4* m4 = (const float4*)&msb[s * L_DIM];
        float mj[16];
        *(float4*)&mj[0]  = m4[0];
        *(float4*)&mj[4]  = m4[1];
        *(float4*)&mj[8]  = m4[2];
        *(float4*)&mj[12] = m4[3];
#pragma unroll
        for (int q = 0; q < 16; ++q) a[q] += msi * mj[q];
      }
      float mpi = sm->mp[i];
#pragma unroll
      for (int q = 0; q < 16; ++q) {
        int jj = (g << 4) + q;
        a[q] = a[q] * (1.0f / (float)S_DIM) - mpi * sm->mp[jj];
        if (i == jj) a[q] += sm->Qs[i];
      }
    }

    chol64_reg(a, sm, i, g);           // Lp
    triinv64_reg(sm, i, g);            // Li = Lp^{-1}

    // yv = Li*mp ; outputs m_p, P_p_chol (=Lb)
    if (tid < L_DIM) {
      float acc = 0.0f;
      int jend = (tid | 31) + 1;
      for (int j = 0; j < jend; ++j) acc += sm->Li[tid * LP + j] * sm->mp[j];
      sm->yv[tid] = acc;
      out_mp[((size_t)b * T_DIM + t) * L_DIM + tid] = sm->mp[tid];
    }
    {
      float* dst = out_Pp + ((size_t)b * T_DIM + t) * (L_DIM * L_DIM);
      for (int idx = tid; idx < 64 * 64; idx += NT) {
        int r = idx >> 6, c2 = idx & 63;
        dst[idx] = sm->Lb[r * LP + c2];
      }
    }
    __syncthreads();

    // hf = Li^T yv + k_t ; J_f = Li^T Li + K K^T into registers
    if (tid < L_DIM) {
      float acc = sm->kt[tid];
      for (int j = iw; j < 64; ++j) acc += sm->Li[j * LP + tid] * sm->yv[j];
      sm->hf[tid] = acc;
    }
    {
      float Ki[R_DIM];
#pragma unroll
      for (int r = 0; r < R_DIM; ++r) Ki[r] = sm->Ksm[i * KP + r];
#pragma unroll
      for (int q = 0; q < 16; ++q) {
        int jj = (g << 4) + q;
        float acc = 0.0f;
#pragma unroll
        for (int r = 0; r < R_DIM; ++r) acc += Ki[r] * sm->Ksm[jj * KP + r];
        a[q] = acc;
      }
      int k0 = (iw > (g << 4)) ? iw : (g << 4);  // warp-uniform; zeros skipped
      for (int k2 = k0; k2 < 64; ++k2) {
        float lvi = sm->Li[k2 * LP + i];
        const float* lr = &sm->Li[k2 * LP + (g << 4)];
#pragma unroll
        for (int q = 0; q < 16; ++q) a[q] += lvi * lr[q];
      }
    }
    __syncthreads();

    chol64_reg(a, sm, i, g);           // Lf
    triinv64_reg(sm, i, g);            // Li = Lf^{-1}

    // yv = Li*hf ; P_f_chol = Li^T
    if (tid < L_DIM) {
      float acc = 0.0f;
      int jend = (tid | 31) + 1;
      for (int j = 0; j < jend; ++j) acc += sm->Li[tid * LP + j] * sm->hf[j];
      sm->yv[tid] = acc;
    }
    {
      float* dst = out_Pf + ((size_t)b * T_DIM + t) * (L_DIM * L_DIM);
      for (int idx = tid; idx < 64 * 64; idx += NT) {
        int r = idx >> 6, c2 = idx & 63;
        dst[idx] = sm->Li[c2 * LP + r];
      }
    }
    __syncthreads();

    // mf = Li^T yv
    if (tid < L_DIM) {
      float acc = 0.0f;
      for (int j = iw; j < 64; ++j) acc += sm->Li[j * LP + tid] * sm->yv[j];
      sm->mf[tid] = acc;
      out_mf[((size_t)b * T_DIM + t) * L_DIM + tid] = acc;
    }
    __syncthreads();

    zf_store(sm, out_z, b, t, tid);
    __syncthreads();
  }
}

extern "C" void kernel_launch(void* const* d_in, const int* in_sizes, int n_in,
                              void* d_out, int out_size) {
  (void)in_sizes; (void)n_in; (void)out_size;
  static int attr_set = 0;
  if (!attr_set) {
    cudaFuncSetAttribute(NonlinearFilter_24721831756601_kernel,
                         cudaFuncAttributeMaxDynamicSharedMemorySize,
                         (int)sizeof(SmemNLF));
    attr_set = 1;
  }
  NonlinearFilter_24721831756601_kernel
      <<<B_DIM, NT, sizeof(SmemNLF)>>>(
          (const float*)d_in[0], (const float*)d_in[1],
          (const float*)d_in[2], (const float*)d_in[3],
          (const float*)d_in[4], (const float*)d_in[5],
          (const float*)d_in[6], (const float*)d_in[7],
          (const float*)d_in[8], (const float*)d_in[9],
          (float*)d_out);
}

// round 12
// speedup vs baseline: 3.7077x; 1.1885x over previous
#include <cuda_runtime.h>
#include <math.h>

#define S_DIM 16
#define B_DIM 128
#define T_DIM 200
#define L_DIM 64
#define R_DIM 16
#define H_DIM 256
#define NT    256
#define LP    65    // padded stride, 64x64 matrices
#define LT    68    // padded stride for LbT (float4 rows)
#define HS    260   // padded stride for hidden
#define KP    17    // padded stride for K tile

struct __align__(16) SmemNLF {
  float w1[L_DIM * H_DIM];
  float w2[H_DIM * L_DIM];
  float b1[H_DIM];
  float b2[L_DIM];
  float zs[S_DIM * L_DIM];
  float hid[S_DIM * HS];
  float ms[S_DIM * L_DIM];
  float Lb[L_DIM * LP];      // cholesky factor, row-major, zeros above diag
  float LbT[L_DIM * LT];     // transposed factor (row j = column j of L)
  float Li[L_DIM * LP];      // inverse factor, zeros above diag
  float Ksm[L_DIM * KP];
  float wsm[S_DIM * L_DIM];
  float colbuf[2][144];      // chol 2-column broadcast (double buffered)
  float ybuf[2][4][72];      // triinv 4-pivot broadcast (double buffered)
  float kt[L_DIM];
  float mp[L_DIM];
  float hf[L_DIM];
  float mf[L_DIM];
  float yv[L_DIM];
  float invd[L_DIM];
  float Qs[L_DIM];
  float m0s[L_DIM];
  float J0s[L_DIM];
  float sqP0[L_DIM];
};

__device__ __forceinline__ float softplus_f(float x) {
  return fmaxf(x, 0.0f) + log1pf(expf(-fabsf(x)));
}

// Register-resident right-looking Cholesky, TWO columns per barrier.
// Thread (i,g) owns A[i][16g+q] in a[16]. Owner broadcasts raw columns j and
// j+1; every thread locally reconstructs the updated column j+1 from the two
// broadcasts and applies a fused rank-2 register update. 32 barriers total.
__device__ __forceinline__ void chol64_reg(float* a, SmemNLF* sm,
                                           const int i, const int g) {
  const int gb = g << 4;
#pragma unroll 1
  for (int jg = 0; jg < 4; ++jg) {
    const bool owner = (g == jg);
#pragma unroll
    for (int q = 0; q < 16; q += 2) {
      const int j = (jg << 4) + q;
      float* cb = sm->colbuf[(q >> 1) & 1];   // col j at [0..], col j+1 at [72..]
      if (owner) { cb[i] = a[q]; cb[72 + i] = a[q + 1]; }
      __syncthreads();
      const float d0   = cb[j];
      const float s0   = rsqrtf(d0);
      const float inv0 = s0 * s0;
      const float t    = cb[j + 1] * inv0;            // A[j+1][j]/d0
      const float d1   = cb[72 + j + 1] - cb[j + 1] * t;
      const float s1   = rsqrtf(d1);
      const float inv1 = s1 * s1;
      if (g == 0) {
        float c0i = cb[i];
        float c1i = cb[72 + i] - c0i * t;
        float lv0 = (i >= j)     ? c0i * s0 : 0.0f;
        float lv1 = (i >= j + 1) ? c1i * s1 : 0.0f;
        sm->Lb[i * LP + j]        = lv0;
        sm->Lb[i * LP + j + 1]    = lv1;
        sm->LbT[j * LT + i]       = lv0;
        sm->LbT[(j + 1) * LT + i] = lv1;
        if (i == j) { sm->invd[j] = s0; sm->invd[j + 1] = s1; }
      }
      if (gb + 15 > j + 1) {            // warp-uniform: group has cols > j+1
        float c0i = cb[i];
        float c1i = cb[72 + i] - c0i * t;
        float f0  = c0i * inv0;
        float f1  = c1i * inv1;
        const float4* v0 = (const float4*)&cb[gb];
        const float4* v1 = (const float4*)&cb[72 + gb];
#pragma unroll
        for (int cq = 0; cq < 4; ++cq) {
          float4 x0 = v0[cq];
          float4 x1 = v1[cq];
          const int k = gb + cq * 4;
          float u;
          if (k + 0 > j + 1) { u = x1.x - x0.x * t; a[cq*4+0] -= f0 * x0.x + f1 * u; }
          if (k + 1 > j + 1) { u = x1.y - x0.y * t; a[cq*4+1] -= f0 * x0.y + f1 * u; }
          if (k + 2 > j + 1) { u = x1.z - x0.z * t; a[cq*4+2] -= f0 * x0.z + f1 * u; }
          if (k + 3 > j + 1) { u = x1.w - x0.w * t; a[cq*4+3] -= f0 * x0.w + f1 * u; }
        }
      }
    }
  }
}

// Register-resident Li = L^{-1} (lower, exact zeros above diagonal),
// FOUR pivots per barrier. Thread (c,p) owns rows [16p,16p+16) of column c
// as deferred residual x[16]. Owner runs a local 4-step forward substitution
// (6 broadcast Lb scalars), publishes 4 y's, consumers do a rank-4 update
// from LbT rows. 16 barriers total.
__device__ __forceinline__ void triinv64_reg(SmemNLF* sm,
                                             const int c, const int p) {
  const int cw = c & 32;                // warp-uniform
  const int pb = p << 4;
  float x[16];
#pragma unroll
  for (int q = 0; q < 16; ++q) x[q] = ((pb + q) == c) ? 1.0f : 0.0f;
  int phase = 0;
#pragma unroll 1
  for (int jg = 0; jg < 4; ++jg) {
    const bool owner = (p == jg);
#pragma unroll
    for (int m = 0; m < 4; ++m, ++phase) {
      const int j0 = (jg << 4) + (m << 2);
      float (*yb)[72] = sm->ybuf[phase & 1];
      if (owner) {
        const int q0 = m << 2;
        float i0 = sm->invd[j0],     i1 = sm->invd[j0 + 1];
        float i2 = sm->invd[j0 + 2], i3 = sm->invd[j0 + 3];
        float l10 = sm->Lb[(j0+1)*LP + j0];
        float l20 = sm->Lb[(j0+2)*LP + j0];
        float l21 = sm->Lb[(j0+2)*LP + j0+1];
        float l30 = sm->Lb[(j0+3)*LP + j0];
        float l31 = sm->Lb[(j0+3)*LP + j0+1];
        float l32 = sm->Lb[(j0+3)*LP + j0+2];
        float y0 = x[q0] * i0;
        float y1 = (x[q0+1] - l10 * y0) * i1;
        float y2 = (x[q0+2] - l20 * y0 - l21 * y1) * i2;
        float y3 = (x[q0+3] - l30 * y0 - l31 * y1 - l32 * y2) * i3;
        yb[0][c] = y0; yb[1][c] = y1; yb[2][c] = y2; yb[3][c] = y3;
        sm->Li[(j0    ) * LP + c] = y0;
        sm->Li[(j0 + 1) * LP + c] = y1;
        sm->Li[(j0 + 2) * LP + c] = y2;
        sm->Li[(j0 + 3) * LP + c] = y3;
      }
      __syncthreads();
      if (j0 + 3 >= cw && pb + 15 > j0 + 3) {   // warp-uniform work filter
        float y0 = yb[0][c], y1 = yb[1][c], y2 = yb[2][c], y3 = yb[3][c];
        const float4* r0 = (const float4*)&sm->LbT[(j0    ) * LT + pb];
        const float4* r1 = (const float4*)&sm->LbT[(j0 + 1) * LT + pb];
        const float4* r2 = (const float4*)&sm->LbT[(j0 + 2) * LT + pb];
        const float4* r3 = (const float4*)&sm->LbT[(j0 + 3) * LT + pb];
#pragma unroll
        for (int cq = 0; cq < 4; ++cq) {
          float4 a0 = r0[cq], a1 = r1[cq], a2 = r2[cq], a3 = r3[cq];
          const int rb = pb + cq * 4;
          if (rb + 0 > j0 + 3) x[cq*4+0] -= a0.x*y0 + a1.x*y1 + a2.x*y2 + a3.x*y3;
          if (rb + 1 > j0 + 3) x[cq*4+1] -= a0.y*y0 + a1.y*y1 + a2.y*y2 + a3.y*y3;
          if (rb + 2 > j0 + 3) x[cq*4+2] -= a0.z*y0 + a1.z*y1 + a2.z*y2 + a3.z*y3;
          if (rb + 3 > j0 + 3) x[cq*4+3] -= a0.w*y0 + a1.w*y1 + a2.w*y2 + a3.w*y3;
        }
      }
    }
  }
}

__device__ __forceinline__ void load_step(SmemNLF* sm,
    const float* __restrict__ gk, const float* __restrict__ gK,
    const float* __restrict__ gw, int b, int t, int tid) {
  if (tid < L_DIM)
    sm->kt[tid] = gk[((size_t)b * T_DIM + t) * L_DIM + tid];
  {
    const float4* src =
        (const float4*)(gK + ((size_t)b * T_DIM + t) * (L_DIM * R_DIM));
    float4 v = src[tid];
    int l = tid >> 2, r = (tid & 3) * 4;
    float* dst = &sm->Ksm[l * KP + r];
    dst[0] = v.x; dst[1] = v.y; dst[2] = v.z; dst[3] = v.w;
  }
  {
    int s = tid >> 4, l4 = (tid & 15) * 4;
    const float4* src = (const float4*)(
        gw + (((size_t)t * S_DIM + s) * B_DIM + b) * L_DIM + l4);
    *(float4*)&sm->wsm[s * L_DIM + l4] = *src;
  }
}

// z_f[s][i] = mf[i] + sum_j Li[j][i]*w[s][j]; writes zs and z_f output.
__device__ __forceinline__ void zf_store(SmemNLF* sm, float* __restrict__ out_z,
                                         int b, int t, int tid) {
  const int i = tid & 63, p = tid >> 6;
  const float base = sm->mf[i];
  float a0 = base, a1 = base, a2 = base, a3 = base;
  const float* wr0 = &sm->wsm[(4 * p + 0) * L_DIM];
  const float* wr1 = &sm->wsm[(4 * p + 1) * L_DIM];
  const float* wr2 = &sm->wsm[(4 * p + 2) * L_DIM];
  const float* wr3 = &sm->wsm[(4 * p + 3) * L_DIM];
  const int j0 = i & 32;
  for (int j = j0; j < 64; ++j) {
    float lv = sm->Li[j * LP + i];
    a0 += lv * wr0[j]; a1 += lv * wr1[j];
    a2 += lv * wr2[j]; a3 += lv * wr3[j];
  }
  float acc[4] = {a0, a1, a2, a3};
#pragma unroll
  for (int q = 0; q < 4; ++q) {
    int s = 4 * p + q;
    sm->zs[s * L_DIM + i] = acc[q];
    out_z[(((size_t)s * B_DIM + b) * T_DIM + t) * L_DIM + i] = acc[q];
  }
}

extern __shared__ float smem_raw_nlf[];

__global__ void __launch_bounds__(NT, 1)
NonlinearFilter_24721831756601_kernel(
    const float* __restrict__ gk, const float* __restrict__ gK,
    const float* __restrict__ glogQ, const float* __restrict__ gm0,
    const float* __restrict__ glogv0, const float* __restrict__ gW1,
    const float* __restrict__ gb1, const float* __restrict__ gW2,
    const float* __restrict__ gb2, const float* __restrict__ gw,
    float* __restrict__ out) {
  SmemNLF* sm = (SmemNLF*)smem_raw_nlf;
  const int tid = threadIdx.x;
  const int b = blockIdx.x;
  const int i = tid & 63;             // owned matrix row (chol) / column (triinv)
  const int g = tid >> 6;             // column group (chol) / row group (triinv)
  const int iw = i & 32;              // warp-uniform floor of i

  const size_t ZN = (size_t)S_DIM * B_DIM * T_DIM * L_DIM;
  const size_t MN = (size_t)B_DIM * T_DIM * L_DIM;
  const size_t PN = (size_t)B_DIM * T_DIM * L_DIM * L_DIM;
  float* out_z  = out;
  float* out_mf = out + ZN;
  float* out_mp = out_mf + MN;
  float* out_Pf = out_mp + MN;
  float* out_Pp = out_Pf + PN;

  for (int idx = tid; idx < L_DIM * H_DIM; idx += NT) sm->w1[idx] = gW1[idx];
  for (int idx = tid; idx < H_DIM * L_DIM; idx += NT) sm->w2[idx] = gW2[idx];
  if (tid < H_DIM) sm->b1[tid] = gb1[tid];
  if (tid < L_DIM) {
    sm->b2[tid]  = gb2[tid];
    sm->Qs[tid]  = softplus_f(glogQ[tid]);
    float p0     = softplus_f(glogv0[tid]);
    sm->J0s[tid] = 1.0f / p0;
    sm->sqP0[tid] = sqrtf(p0);
    sm->m0s[tid] = gm0[tid];
  }
  load_step(sm, gk, gK, gw, b, 0, tid);
  __syncthreads();

  float a[16];                         // register tile A[i][16g+q]

  // ================= t = 0 =================
  {
    float Ki[R_DIM];
#pragma unroll
    for (int r = 0; r < R_DIM; ++r) Ki[r] = sm->Ksm[i * KP + r];
#pragma unroll
    for (int q = 0; q < 16; ++q) {
      int jj = (g << 4) + q;
      float acc = (i == jj) ? sm->J0s[i] : 0.0f;
#pragma unroll
      for (int r = 0; r < R_DIM; ++r) acc += Ki[r] * sm->Ksm[jj * KP + r];
      a[q] = acc;
    }
    if (tid < L_DIM)
      sm->hf[tid] = sm->J0s[tid] * sm->m0s[tid] + sm->kt[tid];

    chol64_reg(a, sm, i, g);           // Lf0
    triinv64_reg(sm, i, g);            // Li = Lf0^{-1}

    if (tid < L_DIM) {
      float acc = 0.0f;
      int jend = (tid | 31) + 1;
      for (int j = 0; j < jend; ++j) acc += sm->Li[tid * LP + j] * sm->hf[j];
      sm->yv[tid] = acc;
      out_mp[((size_t)b * T_DIM + 0) * L_DIM + tid] = sm->m0s[tid];
    }
    {
      float* dst = out_Pp + ((size_t)b * T_DIM + 0) * (L_DIM * L_DIM);
      for (int idx = tid; idx < 64 * 64; idx += NT) {
        int r = idx >> 6, c2 = idx & 63;
        dst[idx] = (r == c2) ? sm->sqP0[r] : 0.0f;
      }
    }
    __syncthreads();
    if (tid < L_DIM) {
      float acc = 0.0f;
      for (int j = iw; j < 64; ++j) acc += sm->Li[j * LP + tid] * sm->yv[j];
      sm->mf[tid] = acc;
      out_mf[((size_t)b * T_DIM + 0) * L_DIM + tid] = acc;
    }
    {
      float* dst = out_Pf + ((size_t)b * T_DIM + 0) * (L_DIM * L_DIM);
      for (int idx = tid; idx < 64 * 64; idx += NT) {
        int r = idx >> 6, c2 = idx & 63;
        dst[idx] = sm->Li[c2 * LP + r];
      }
    }
    __syncthreads();
    zf_store(sm, out_z, b, 0, tid);
    __syncthreads();
  }

  // ================= t = 1 .. T-1 =================
  for (int t = 1; t < T_DIM; ++t) {
    load_step(sm, gk, gK, gw, b, t, tid);

    // ---- MLP layer 1 ----
    {
      float acc[S_DIM];
      float bb = sm->b1[tid];
#pragma unroll
      for (int s = 0; s < S_DIM; ++s) acc[s] = bb;
      for (int l = 0; l < L_DIM; l += 4) {
        float wa = sm->w1[(l + 0) * H_DIM + tid];
        float wb = sm->w1[(l + 1) * H_DIM + tid];
        float wc = sm->w1[(l + 2) * H_DIM + tid];
        float wd = sm->w1[(l + 3) * H_DIM + tid];
#pragma unroll
        for (int s = 0; s < S_DIM; ++s) {
          float4 z4 = *(const float4*)&sm->zs[s * L_DIM + l];
          acc[s] += z4.x * wa + z4.y * wb + z4.z * wc + z4.w * wd;
        }
      }
#pragma unroll
      for (int s = 0; s < S_DIM; ++s) sm->hid[s * HS + tid] = tanhf(acc[s]);
    }
    __syncthreads();

    // ---- MLP layer 2 ----
    {
      const int j = tid & 63, p = tid >> 6;
      float acc4[4];
      float bb = sm->b2[j];
#pragma unroll
      for (int q = 0; q < 4; ++q) acc4[q] = bb;
      for (int h = 0; h < H_DIM; h += 4) {
        float wa = sm->w2[(h + 0) * L_DIM + j];
        float wb = sm->w2[(h + 1) * L_DIM + j];
        float wc = sm->w2[(h + 2) * L_DIM + j];
        float wd = sm->w2[(h + 3) * L_DIM + j];
#pragma unroll
        for (int q = 0; q < 4; ++q) {
          float4 h4 = *(const float4*)&sm->hid[(4 * p + q) * HS + h];
          acc4[q] += h4.x * wa + h4.y * wb + h4.z * wc + h4.w * wd;
        }
      }
#pragma unroll
      for (int q = 0; q < 4; ++q) sm->ms[(4 * p + q) * L_DIM + j] = acc4[q];
    }
    __syncthreads();

    // ---- m_p ----
    if (tid < L_DIM) {
      float acc = 0.0f;
#pragma unroll
      for (int s = 0; s < S_DIM; ++s) acc += sm->ms[s * L_DIM + tid];
      sm->mp[tid] = acc * (1.0f / (float)S_DIM);
    }
    __syncthreads();

    // ---- P_p into registers: a[q] = Q_diag + Ezz - mp mp^T ----
    {
      const float* msb = &sm->ms[(g << 4)];
#pragma unroll
      for (int q = 0; q < 16; ++q) a[q] = 0.0f;
#pragma unroll
      for (int s = 0; s < S_DIM; ++s) {
        float msi = sm->ms[s * L_DIM + i];
        const float4* m4 = (const float4*)&msb[s * L_DIM];
        float mj[16];
        *(float4*)&mj[0]  = m4[0];
        *(float4*)&mj[4]  = m4[1];
        *(float4*)&mj[8]  = m4[2];
        *(float4*)&mj[12] = m4[3];
#pragma unroll
        for (int q = 0; q < 16; ++q) a[q] += msi * mj[q];
      }
      float mpi = sm->mp[i];
#pragma unroll
      for (int q = 0; q < 16; ++q) {
        int jj = (g << 4) + q;
        a[q] = a[q] * (1.0f / (float)S_DIM) - mpi * sm->mp[jj];
        if (i == jj) a[q] += sm->Qs[i];
      }
    }

    chol64_reg(a, sm, i, g);           // Lp
    triinv64_reg(sm, i, g);            // Li = Lp^{-1}

    // yv = Li*mp ; outputs m_p, P_p_chol (=Lb)
    if (tid < L_DIM) {
      float acc = 0.0f;
      int jend = (tid | 31) + 1;
      for (int j = 0; j < jend; ++j) acc += sm->Li[tid * LP + j] * sm->mp[j];
      sm->yv[tid] = acc;
      out_mp[((size_t)b * T_DIM + t) * L_DIM + tid] = sm->mp[tid];
    }
    {
      float* dst = out_Pp + ((size_t)b * T_DIM + t) * (L_DIM * L_DIM);
      for (int idx = tid; idx < 64 * 64; idx += NT) {
        int r = idx >> 6, c2 = idx & 63;
        dst[idx] = sm->Lb[r * LP + c2];
      }
    }
    __syncthreads();

    // hf = Li^T yv + k_t ; J_f = Li^T Li + K K^T into registers
    if (tid < L_DIM) {
      float acc = sm->kt[tid];
      for (int j = iw; j < 64; ++j) acc += sm->Li[j * LP + tid] * sm->yv[j];
      sm->hf[tid] = acc;
    }
    {
      float Ki[R_DIM];
#pragma unroll
      for (int r = 0; r < R_DIM; ++r) Ki[r] = sm->Ksm[i * KP + r];
#pragma unroll
      for (int q = 0; q < 16; ++q) {
        int jj = (g << 4) + q;
        float acc = 0.0f;
#pragma unroll
        for (int r = 0; r < R_DIM; ++r) acc += Ki[r] * sm->Ksm[jj * KP + r];
        a[q] = acc;
      }
      int k0 = (iw > (g << 4)) ? iw : (g << 4);  // warp-uniform; zeros skipped
      for (int k2 = k0; k2 < 64; ++k2) {
        float lvi = sm->Li[k2 * LP + i];
        const float* lr = &sm->Li[k2 * LP + (g << 4)];
#pragma unroll
        for (int q = 0; q < 16; ++q) a[q] += lvi * lr[q];
      }
    }
    __syncthreads();

    chol64_reg(a, sm, i, g);           // Lf
    triinv64_reg(sm, i, g);            // Li = Lf^{-1}

    // yv = Li*hf ; P_f_chol = Li^T
    if (tid < L_DIM) {
      float acc = 0.0f;
      int jend = (tid | 31) + 1;
      for (int j = 0; j < jend; ++j) acc += sm->Li[tid * LP + j] * sm->hf[j];
      sm->yv[tid] = acc;
    }
    {
      float* dst = out_Pf + ((size_t)b * T_DIM + t) * (L_DIM * L_DIM);
      for (int idx = tid; idx < 64 * 64; idx += NT) {
        int r = idx >> 6, c2 = idx & 63;
        dst[idx] = sm->Li[c2 * LP + r];
      }
    }
    __syncthreads();

    // mf = Li^T yv
    if (tid < L_DIM) {
      float acc = 0.0f;
      for (int j = iw; j < 64; ++j) acc += sm->Li[j * LP + tid] * sm->yv[j];
      sm->mf[tid] = acc;
      out_mf[((size_t)b * T_DIM + t) * L_DIM + tid] = acc;
    }
    __syncthreads();

    zf_store(sm, out_z, b, t, tid);
    __syncthreads();
  }
}

extern "C" void kernel_launch(void* const* d_in, const int* in_sizes, int n_in,
                              void* d_out, int out_size) {
  (void)in_sizes; (void)n_in; (void)out_size;
  static int attr_set = 0;
  if (!attr_set) {
    cudaFuncSetAttribute(NonlinearFilter_24721831756601_kernel,
                         cudaFuncAttributeMaxDynamicSharedMemorySize,
                         (int)sizeof(SmemNLF));
    attr_set = 1;
  }
  NonlinearFilter_24721831756601_kernel
      <<<B_DIM, NT, sizeof(SmemNLF)>>>(
          (const float*)d_in[0], (const float*)d_in[1],
          (const float*)d_in[2], (const float*)d_in[3],
          (const float*)d_in[4], (const float*)d_in[5],
          (const float*)d_in[6], (const float*)d_in[7],
          (const float*)d_in[8], (const float*)d_in[9],
          (float*)d_out);
}